// round 2
// baseline (speedup 1.0000x reference)
#include <cuda_runtime.h>
#include <cuda_bf16.h>
#include <math.h>

#define T_FRAMES 2000
#define NB 4
#define NHARM 6
#define T_AUD 960000
#define NCHUNK 3750   // T_AUD / 256

// ---------------- scratch (no allocs allowed) ----------------
__device__ float g_amp_mod[NB * NHARM * T_FRAMES];
__device__ float g_totals[NB * NCHUNK];
__device__ float g_carries[NB * NCHUNK];

// ---------------- helpers ----------------
__device__ __forceinline__ void interp_coords(int i, int& i0, int& i1, float& w) {
    float pos = ((float)i + 0.5f) * (1.0f / 480.0f) - 0.5f;
    pos = fminf(fmaxf(pos, 0.0f), 1999.0f);
    i0 = (int)pos;                 // floor (pos >= 0)
    i1 = min(i0 + 1, 1999);
    w = pos - (float)i0;
}

// ---------------- kernel 1: conv1 + SiLU + conv2 ----------------
// block: 256 threads, handles batch b and a 64-frame tile (all 32 mid channels)
__global__ void __launch_bounds__(256) conv_kernel(
    const float* __restrict__ f0, const float* __restrict__ mel,
    const float* __restrict__ w1, const float* __restrict__ b1,
    const float* __restrict__ w2, const float* __restrict__ b2)
{
    __shared__ float sx[129 * 68];   // input tile (t0-2 .. t0+65), zero-padded
    __shared__ float sh[32 * 64];    // silu(conv1) tile
    const int b   = blockIdx.y;
    const int t0  = blockIdx.x * 64;
    const int tid = threadIdx.x;

    for (int e = tid; e < 129 * 68; e += 256) {
        int ic = e / 68, tt = e - ic * 68;
        int t = t0 + tt - 2;
        float v = 0.0f;
        if (t >= 0 && t < T_FRAMES)
            v = (ic == 0) ? f0[b * T_FRAMES + t]
                          : mel[(b * 128 + (ic - 1)) * T_FRAMES + t];
        sx[e] = v;
    }
    __syncthreads();

    const int c  = tid >> 3;       // mid channel 0..31
    const int tg = tid & 7;        // t group
    const int tb = tg * 8;         // base t_local

    float acc[8];
    {
        float bias = b1[c];
#pragma unroll
        for (int j = 0; j < 8; j++) acc[j] = bias;
    }
    for (int ic = 0; ic < 129; ic++) {
        const float* xr = &sx[ic * 68 + tb];
        const float* wr = &w1[(c * 129 + ic) * 5];
        float wv0 = wr[0], wv1 = wr[1], wv2 = wr[2], wv3 = wr[3], wv4 = wr[4];
        float xv[12];
#pragma unroll
        for (int m = 0; m < 12; m++) xv[m] = xr[m];
#pragma unroll
        for (int j = 0; j < 8; j++) {
            float a = acc[j];
            a = fmaf(wv0, xv[j + 0], a);
            a = fmaf(wv1, xv[j + 1], a);
            a = fmaf(wv2, xv[j + 2], a);
            a = fmaf(wv3, xv[j + 3], a);
            a = fmaf(wv4, xv[j + 4], a);
            acc[j] = a;
        }
    }
#pragma unroll
    for (int j = 0; j < 8; j++) {
        float h = acc[j];
        sh[c * 64 + tb + j] = h / (1.0f + __expf(-h));   // silu
    }
    __syncthreads();

    // conv2: 6 x 64 outputs
    for (int o = tid; o < NHARM * 64; o += 256) {
        int nh = o >> 6, tl = o & 63;
        int t = t0 + tl;
        if (t < T_FRAMES) {
            float s = b2[nh];
            const float* wp = &w2[nh * 32];
#pragma unroll
            for (int cc = 0; cc < 32; cc++)
                s = fmaf(wp[cc], sh[cc * 64 + tl], s);
            g_amp_mod[(b * NHARM + nh) * T_FRAMES + t] = s;
        }
    }
}

// ---------------- kernel 2: per-chunk phase-increment totals ----------------
__global__ void __launch_bounds__(256) totals_kernel(const float* __restrict__ f0)
{
    const int b = blockIdx.y;
    const int i = blockIdx.x * 256 + threadIdx.x;
    int i0, i1; float w;
    interp_coords(i, i0, i1, w);
    const float* f0b = f0 + b * T_FRAMES;
    float f0v = f0b[i0] * (1.0f - w) + f0b[i1] * w;
    float inc = f0v * (1.0f / 48000.0f);

#pragma unroll
    for (int off = 16; off; off >>= 1) inc += __shfl_down_sync(0xffffffffu, inc, off);
    __shared__ float ws[8];
    int lane = threadIdx.x & 31, wid = threadIdx.x >> 5;
    if (lane == 0) ws[wid] = inc;
    __syncthreads();
    if (threadIdx.x == 0) {
        float s = 0.0f;
#pragma unroll
        for (int k = 0; k < 8; k++) s += ws[k];
        g_totals[b * NCHUNK + blockIdx.x] = s;
    }
}

// ---------------- kernel 3: exclusive wrapped-carry scan (double) ----------------
__global__ void __launch_bounds__(1024) scan_kernel()
{
    const int b = blockIdx.x;
    const int tid = threadIdx.x;
    const int PER = 4;                       // 1024*4 >= 3750
    const int s0 = tid * PER;

    float tl[PER];
    double loc = 0.0;
#pragma unroll
    for (int j = 0; j < PER; j++) {
        int idx = s0 + j;
        float t = (idx < NCHUNK) ? g_totals[b * NCHUNK + idx] : 0.0f;
        tl[j] = t;
        loc += (double)t;
    }
    __shared__ double sd[1024];
    sd[tid] = loc;
    __syncthreads();
    for (int off = 1; off < 1024; off <<= 1) {
        double add = (tid >= off) ? sd[tid - off] : 0.0;
        __syncthreads();
        sd[tid] += add;
        __syncthreads();
    }
    double base = (tid > 0) ? sd[tid - 1] : 0.0;   // exclusive prefix
#pragma unroll
    for (int j = 0; j < PER; j++) {
        int idx = s0 + j;
        if (idx < NCHUNK)
            g_carries[b * NCHUNK + idx] = (float)(base - floor(base));
        base += (double)tl[j];
    }
}

// ---------------- kernel 4: main synthesis ----------------
// block = one 256-sample chunk of one batch
__global__ void __launch_bounds__(256) main_kernel(
    const float* __restrict__ f0, const float* __restrict__ noise,
    const float* __restrict__ amp_logscale, const float* __restrict__ phase_offset,
    const float* __restrict__ lnv, const float* __restrict__ lnu,
    float* __restrict__ out)
{
    const int b   = blockIdx.y;
    const int ch  = blockIdx.x;                // chunk index
    const int tid = threadIdx.x;
    const int i   = ch * 256 + tid;

    int i0, i1; float w;
    interp_coords(i, i0, i1, w);
    const float* f0b = f0 + b * T_FRAMES;
    float f0v = f0b[i0] * (1.0f - w) + f0b[i1] * w;
    float inc = f0v * (1.0f / 48000.0f);

    // block-wide inclusive scan of phase increments
    const unsigned FULL = 0xffffffffu;
    int lane = tid & 31, wid = tid >> 5;
    float v = inc;
#pragma unroll
    for (int off = 1; off < 32; off <<= 1) {
        float n = __shfl_up_sync(FULL, v, off);
        if (lane >= off) v += n;
    }
    __shared__ float ws[8];
    if (lane == 31) ws[wid] = v;
    __syncthreads();
    if (wid == 0) {
        float x = (lane < 8) ? ws[lane] : 0.0f;
#pragma unroll
        for (int off = 1; off < 8; off <<= 1) {
            float n = __shfl_up_sync(FULL, x, off);
            if (lane >= off) x += n;
        }
        if (lane < 8) ws[lane] = x;
    }
    __syncthreads();
    float cum = v + (wid ? ws[wid - 1] : 0.0f);

    float phase = cum + g_carries[b * NCHUNK + ch];
    phase -= floorf(phase);                   // fmod(x, 1) for x >= 0

    float voiced = (f0v > 1.0f) ? 1.0f : 0.0f;

    // noise channel (ch 6)
    float namp = (voiced > 0.0f) ? __expf(lnv[0]) : __expf(lnu[0]);
    out[(size_t)(b * 7 + 6) * T_AUD + i] = noise[(size_t)b * T_AUD + i] * namp;

    const float* ab = g_amp_mod + b * NHARM * T_FRAMES;
#pragma unroll
    for (int h = 0; h < NHARM; h++) {
        float k  = (float)(h + 1);
        float am = ab[h * T_FRAMES + i0] * (1.0f - w) + ab[h * T_FRAMES + i1] * w;
        float s  = 2.0f / (1.0f + __expf(-am));
        float aa = 1.0f / (1.0f + __expf(-(24000.0f - k * f0v) * (1.0f / 1200.0f)));
        float u  = fmaf(k, phase, phase_offset[h]);
        float r  = u - rintf(u);              // [-0.5, 0.5] -> arg in [-pi, pi]
        float sv = __sinf(6.283185307179586f * r);
        out[(size_t)(b * 7 + h) * T_AUD + i] =
            sv * __expf(amp_logscale[h]) * s * aa * voiced;
    }
}

// ---------------- launcher ----------------
extern "C" void kernel_launch(void* const* d_in, const int* in_sizes, int n_in,
                              void* d_out, int out_size)
{
    const float* f0    = (const float*)d_in[0];
    const float* mel   = (const float*)d_in[1];
    const float* noise = (const float*)d_in[2];
    const float* w1    = (const float*)d_in[3];
    const float* b1    = (const float*)d_in[4];
    const float* w2    = (const float*)d_in[5];
    const float* b2    = (const float*)d_in[6];
    const float* als   = (const float*)d_in[7];
    const float* pho   = (const float*)d_in[8];
    const float* lnv   = (const float*)d_in[9];
    const float* lnu   = (const float*)d_in[10];
    float* out = (float*)d_out;

    conv_kernel  <<<dim3(32, NB),     256>>>(f0, mel, w1, b1, w2, b2);
    totals_kernel<<<dim3(NCHUNK, NB), 256>>>(f0);
    scan_kernel  <<<NB, 1024>>>();
    main_kernel  <<<dim3(NCHUNK, NB), 256>>>(f0, noise, als, pho, lnv, lnu, out);
}

// round 3
// speedup vs baseline: 1.2764x; 1.2764x over previous
#include <cuda_runtime.h>
#include <cuda_bf16.h>
#include <math.h>

#define T_FRAMES 2000
#define NB 4
#define NHARM 6
#define T_AUD 960000
#define NG 7500                 // 128-sample carry groups per batch
#define GRP 128
#define SCALE_POS (2000.0f/960000.0f)
#define INV_SR (1.0f/48000.0f)
#define TWO_PI_F 6.2831853071795864769f

// ---------------- scratch ----------------
__device__ float g_amp[NB * T_FRAMES * 8];   // padded [b][t][8], ch 0..5 valid
__device__ float g_tot[NB * NG];
__device__ float g_carry[NB * NG];
__device__ float g_consts[16];               // [0..5]=A_h, [6..11]=B_h, [12]=nv, [13]=nu

// ---------------- kernel A: conv (blocks 0..127) + group totals (rest) ----------------
__global__ void __launch_bounds__(256) prep_kernel(
    const float* __restrict__ f0, const float* __restrict__ mel,
    const float* __restrict__ w1, const float* __restrict__ b1,
    const float* __restrict__ w2, const float* __restrict__ b2)
{
    __shared__ float sx[129 * 68];
    __shared__ float sh[32 * 64];
    const int tid = threadIdx.x;

    if (blockIdx.x < 128) {
        // ---- conv role: conv1(129->32,k5) + SiLU + conv2(32->6,k1) ----
        const int b  = blockIdx.x >> 5;
        const int t0 = (blockIdx.x & 31) * 64;

        for (int e = tid; e < 129 * 68; e += 256) {
            int ic = e / 68, tt = e - ic * 68;
            int t = t0 + tt - 2;
            float v = 0.0f;
            if (t >= 0 && t < T_FRAMES)
                v = (ic == 0) ? f0[b * T_FRAMES + t]
                              : mel[(b * 128 + (ic - 1)) * T_FRAMES + t];
            sx[e] = v;
        }
        __syncthreads();

        const int c  = tid >> 3;        // mid channel 0..31
        const int tb = (tid & 7) * 8;   // base t_local

        float acc[8];
        {
            float bias = b1[c];
#pragma unroll
            for (int j = 0; j < 8; j++) acc[j] = bias;
        }
        for (int ic = 0; ic < 129; ic++) {
            const float4* xr4 = (const float4*)&sx[ic * 68 + tb];
            float4 xa = xr4[0], xb = xr4[1], xc = xr4[2];
            float xv[12] = {xa.x, xa.y, xa.z, xa.w, xb.x, xb.y, xb.z, xb.w,
                            xc.x, xc.y, xc.z, xc.w};
            const float* wr = &w1[(c * 129 + ic) * 5];
            float wv0 = wr[0], wv1 = wr[1], wv2 = wr[2], wv3 = wr[3], wv4 = wr[4];
#pragma unroll
            for (int j = 0; j < 8; j++) {
                float a = acc[j];
                a = fmaf(wv0, xv[j + 0], a);
                a = fmaf(wv1, xv[j + 1], a);
                a = fmaf(wv2, xv[j + 2], a);
                a = fmaf(wv3, xv[j + 3], a);
                a = fmaf(wv4, xv[j + 4], a);
                acc[j] = a;
            }
        }
#pragma unroll
        for (int j = 0; j < 8; j++) {
            float h = acc[j];
            sh[c * 64 + tb + j] = h / (1.0f + __expf(-h));
        }
        __syncthreads();

        for (int o = tid; o < NHARM * 64; o += 256) {
            int nh = o >> 6, tl = o & 63;
            int t = t0 + tl;
            if (t < T_FRAMES) {
                float s = b2[nh];
                const float* wp = &w2[nh * 32];
#pragma unroll
                for (int cc = 0; cc < 32; cc++)
                    s = fmaf(wp[cc], sh[cc * 64 + tl], s);
                g_amp[((size_t)b * T_FRAMES + t) * 8 + nh] = s;
            }
        }
    } else {
        // ---- totals role: one warp = one 128-sample group ----
        int idx  = blockIdx.x - 128;           // 0..3749
        int warp = tid >> 5, lane = tid & 31;
        int gg = idx * 8 + warp;               // 0..29999
        int b = gg / NG;
        int g = gg - b * NG;
        const float* f0b = f0 + b * T_FRAMES;
        int base = g * GRP + lane * 4;
        float s = 0.0f;
#pragma unroll
        for (int j = 0; j < 4; j++) {
            int i = base + j;
            float pos = fmaf((float)i + 0.5f, SCALE_POS, -0.5f);
            pos = fminf(fmaxf(pos, 0.0f), 1999.0f);
            int i0 = (int)pos;
            int i1 = min(i0 + 1, 1999);
            float w = pos - (float)i0;
            float v = f0b[i0] * (1.0f - w) + f0b[i1] * w;
            s += v * INV_SR;
        }
#pragma unroll
        for (int off = 16; off; off >>= 1)
            s += __shfl_down_sync(0xffffffffu, s, off);
        if (lane == 0) g_tot[b * NG + g] = s;
    }
}

// ---------------- kernel B: double exclusive wrapped scan + constants ----------------
__global__ void __launch_bounds__(1024) scan_kernel(
    const float* __restrict__ als, const float* __restrict__ pho,
    const float* __restrict__ lnv, const float* __restrict__ lnu)
{
    const int b = blockIdx.x;
    const int tid = threadIdx.x;

    if (b == 0 && tid < NHARM) {
        float e  = expf(als[tid]);
        float ph = TWO_PI_F * pho[tid];
        g_consts[tid]     = e * cosf(ph);
        g_consts[6 + tid] = e * sinf(ph);
        if (tid == 0) { g_consts[12] = expf(lnv[0]); g_consts[13] = expf(lnu[0]); }
    }

    const int PER = 8;                      // 1024*8 >= 7500
    const int s0 = tid * PER;
    float tl[PER];
    double loc = 0.0;
#pragma unroll
    for (int j = 0; j < PER; j++) {
        int idx = s0 + j;
        float t = (idx < NG) ? g_tot[b * NG + idx] : 0.0f;
        tl[j] = t;
        loc += (double)t;
    }
    __shared__ double sd[1024];
    sd[tid] = loc;
    __syncthreads();
    for (int off = 1; off < 1024; off <<= 1) {
        double add = (tid >= off) ? sd[tid - off] : 0.0;
        __syncthreads();
        sd[tid] += add;
        __syncthreads();
    }
    double base = (tid > 0) ? sd[tid - 1] : 0.0;
#pragma unroll
    for (int j = 0; j < PER; j++) {
        int idx = s0 + j;
        if (idx < NG)
            g_carry[b * NG + idx] = (float)(base - floor(base));
        base += (double)tl[j];
    }
}

// ---------------- kernel C: main synthesis ----------------
// block = 128 threads; warp = one 128-sample group; thread = 4 samples
__global__ void __launch_bounds__(128) main_kernel(
    const float* __restrict__ f0, const float* __restrict__ noise,
    float* __restrict__ out)
{
    const int b    = blockIdx.y;
    const int warp = threadIdx.x >> 5;
    const int lane = threadIdx.x & 31;
    const int g    = blockIdx.x * 4 + warp;       // carry group 0..7499
    const int base = g * GRP + lane * 4;
    const float* f0b = f0 + b * T_FRAMES;

    float inc[4], f0v[4], wfr[4];
    int   ia[4];
#pragma unroll
    for (int j = 0; j < 4; j++) {
        int i = base + j;
        float pos = fmaf((float)i + 0.5f, SCALE_POS, -0.5f);
        pos = fminf(fmaxf(pos, 0.0f), 1999.0f);
        int i0 = (int)pos;
        int i1 = min(i0 + 1, 1999);
        float w = pos - (float)i0;
        ia[j] = i0; wfr[j] = w;
        float v = f0b[i0] * (1.0f - w) + f0b[i1] * w;
        f0v[j] = v;
        inc[j] = v * INV_SR;
    }

    float inc4 = ((inc[0] + inc[1]) + inc[2]) + inc[3];
    const unsigned FULL = 0xffffffffu;
    float v = inc4;
#pragma unroll
    for (int off = 1; off < 32; off <<= 1) {
        float n = __shfl_up_sync(FULL, v, off);
        if (lane >= off) v += n;
    }
    float running = g_carry[b * NG + g] + (v - inc4);   // exclusive prefix + carry

    float cA[6], cB[6];
#pragma unroll
    for (int h = 0; h < 6; h++) { cA[h] = g_consts[h]; cB[h] = g_consts[6 + h]; }
    const float nv = g_consts[12], nu = g_consts[13];

    float4 nz = *(const float4*)(noise + (size_t)b * T_AUD + base);
    const float* nzp = &nz.x;

    float och[7][4];
#pragma unroll
    for (int j = 0; j < 4; j++) {
        running += inc[j];
        float ph = running - floorf(running);          // [0,1)
        float r  = ph - rintf(ph);                     // [-0.5, 0.5]
        float s1, c1;
        __sincosf(TWO_PI_F * r, &s1, &c1);
        float voiced = (f0v[j] > 1.0f) ? 1.0f : 0.0f;

        const float* ap = g_amp + ((size_t)b * T_FRAMES + ia[j]) * 8;
        int i1 = min(ia[j] + 1, 1999);
        const float* aq = g_amp + ((size_t)b * T_FRAMES + i1) * 8;
        float4 u0 = *(const float4*)ap;
        float4 u1 = *(const float4*)(ap + 4);
        float4 p0 = *(const float4*)aq;
        float4 p1 = *(const float4*)(aq + 4);
        float w = wfr[j], iw = 1.0f - w;
        float am[6] = { u0.x * iw + p0.x * w, u0.y * iw + p0.y * w,
                        u0.z * iw + p0.z * w, u0.w * iw + p0.w * w,
                        u1.x * iw + p1.x * w, u1.y * iw + p1.y * w };

        float sk = s1, ck = c1;
#pragma unroll
        for (int h = 0; h < 6; h++) {
            if (h) {
                float t = sk * c1 + ck * s1;
                ck = ck * c1 - sk * s1;
                sk = t;
            }
            float e    = __expf(-am[h]);
            float sig2 = __fdividef(2.0f, 1.0f + e);
            och[h][j] = (sk * cA[h] + ck * cB[h]) * (sig2 * voiced);
        }
        float na = (voiced > 0.0f) ? nv : nu;
        och[6][j] = nzp[j] * na;
    }

#pragma unroll
    for (int h = 0; h < 7; h++) {
        float4 o = make_float4(och[h][0], och[h][1], och[h][2], och[h][3]);
        *(float4*)(out + ((size_t)(b * 7 + h)) * T_AUD + base) = o;
    }
}

// ---------------- launcher ----------------
extern "C" void kernel_launch(void* const* d_in, const int* in_sizes, int n_in,
                              void* d_out, int out_size)
{
    const float* f0    = (const float*)d_in[0];
    const float* mel   = (const float*)d_in[1];
    const float* noise = (const float*)d_in[2];
    const float* w1    = (const float*)d_in[3];
    const float* b1    = (const float*)d_in[4];
    const float* w2    = (const float*)d_in[5];
    const float* b2    = (const float*)d_in[6];
    const float* als   = (const float*)d_in[7];
    const float* pho   = (const float*)d_in[8];
    const float* lnv   = (const float*)d_in[9];
    const float* lnu   = (const float*)d_in[10];
    float* out = (float*)d_out;

    prep_kernel<<<128 + 3750, 256>>>(f0, mel, w1, b1, w2, b2);
    scan_kernel<<<NB, 1024>>>(als, pho, lnv, lnu);
    main_kernel<<<dim3(1875, NB), 128>>>(f0, noise, out);
}

// round 4
// speedup vs baseline: 1.3927x; 1.0911x over previous
#include <cuda_runtime.h>
#include <cuda_bf16.h>
#include <math.h>

#define T_FRAMES 2000
#define NB 4
#define NHARM 6
#define T_AUD 960000
#define NG 7500                 // 128-sample carry groups per batch
#define GRP 128
#define SCALE_POS (2000.0f/960000.0f)
#define INV_SR (1.0f/48000.0f)
#define TWO_PI_F 6.2831853071795864769f

#define CT 32                   // conv tile frames
#define NTILE 63                // ceil(2000/32)

// ---------------- scratch ----------------
__device__ float g_amp[NB * T_FRAMES * 8];   // padded [b][t][8], ch 0..5 valid
__device__ float g_tot[NB * NG];
__device__ float g_carry[NB * NG];
__device__ float g_consts[16];               // [0..5]=A_h, [6..11]=B_h, [12]=nv, [13]=nu

// ---------------- kernel 1: conv1 + SiLU + conv2 ----------------
// block = 32-frame tile of one batch; 256 threads = 32 channels x 8 t-groups (4 t each)
__global__ void __launch_bounds__(256) conv_kernel(
    const float* __restrict__ f0, const float* __restrict__ mel,
    const float* __restrict__ w1, const float* __restrict__ b1,
    const float* __restrict__ w2, const float* __restrict__ b2)
{
    __shared__ float sx[129 * 36];   // frames t0-2 .. t0+33, zero padded
    __shared__ float sh[32 * 32];
    const int b   = blockIdx.y;
    const int t0  = blockIdx.x * CT;
    const int tid = threadIdx.x;

    for (int e = tid; e < 129 * 36; e += 256) {
        int ic = e / 36, tt = e - ic * 36;
        int t = t0 + tt - 2;
        float v = 0.0f;
        if (t >= 0 && t < T_FRAMES)
            v = (ic == 0) ? f0[b * T_FRAMES + t]
                          : mel[(b * 128 + (ic - 1)) * T_FRAMES + t];
        sx[e] = v;
    }
    __syncthreads();

    const int c  = tid >> 3;        // channel 0..31
    const int tb = (tid & 7) * 4;   // base t_local 0..28

    float acc0, acc1, acc2, acc3;
    acc0 = acc1 = acc2 = acc3 = b1[c];

    const float* wbase = w1 + c * 129 * 5;
#pragma unroll 2
    for (int ic = 0; ic < 129; ic++) {
        const float4* xr4 = (const float4*)&sx[ic * 36 + tb];
        float4 xa = xr4[0], xb = xr4[1];
        const float* wr = wbase + ic * 5;
        float w0 = __ldg(wr + 0), w1v = __ldg(wr + 1), w2v = __ldg(wr + 2),
              w3 = __ldg(wr + 3), w4 = __ldg(wr + 4);
        acc0 = fmaf(w0, xa.x, acc0); acc0 = fmaf(w1v, xa.y, acc0);
        acc0 = fmaf(w2v, xa.z, acc0); acc0 = fmaf(w3, xa.w, acc0);
        acc0 = fmaf(w4, xb.x, acc0);
        acc1 = fmaf(w0, xa.y, acc1); acc1 = fmaf(w1v, xa.z, acc1);
        acc1 = fmaf(w2v, xa.w, acc1); acc1 = fmaf(w3, xb.x, acc1);
        acc1 = fmaf(w4, xb.y, acc1);
        acc2 = fmaf(w0, xa.z, acc2); acc2 = fmaf(w1v, xa.w, acc2);
        acc2 = fmaf(w2v, xb.x, acc2); acc2 = fmaf(w3, xb.y, acc2);
        acc2 = fmaf(w4, xb.z, acc2);
        acc3 = fmaf(w0, xa.w, acc3); acc3 = fmaf(w1v, xb.x, acc3);
        acc3 = fmaf(w2v, xb.y, acc3); acc3 = fmaf(w3, xb.z, acc3);
        acc3 = fmaf(w4, xb.w, acc3);
    }
    sh[c * 32 + tb + 0] = acc0 / (1.0f + __expf(-acc0));
    sh[c * 32 + tb + 1] = acc1 / (1.0f + __expf(-acc1));
    sh[c * 32 + tb + 2] = acc2 / (1.0f + __expf(-acc2));
    sh[c * 32 + tb + 3] = acc3 / (1.0f + __expf(-acc3));
    __syncthreads();

    // conv2: 6 x 32 outputs
    if (tid < NHARM * 32) {
        int nh = tid >> 5, tl = tid & 31;
        int t = t0 + tl;
        if (t < T_FRAMES) {
            float s = b2[nh];
            const float* wp = &w2[nh * 32];
#pragma unroll
            for (int cc = 0; cc < 32; cc++)
                s = fmaf(wp[cc], sh[cc * 32 + tl], s);
            g_amp[((size_t)b * T_FRAMES + t) * 8 + nh] = s;
        }
    }
}

// ---------------- kernel 2: per-group phase-increment totals ----------------
// no smem: full occupancy; warp = one 128-sample group
__global__ void __launch_bounds__(256) totals_kernel(const float* __restrict__ f0)
{
    int warp = threadIdx.x >> 5, lane = threadIdx.x & 31;
    int gg = blockIdx.x * 8 + warp;        // 0..29999
    int b = gg / NG;
    int g = gg - b * NG;
    const float* f0b = f0 + b * T_FRAMES;
    int base = g * GRP + lane * 4;
    float s = 0.0f;
#pragma unroll
    for (int j = 0; j < 4; j++) {
        int i = base + j;
        float pos = fmaf((float)i + 0.5f, SCALE_POS, -0.5f);
        pos = fminf(fmaxf(pos, 0.0f), 1999.0f);
        int i0 = (int)pos;
        int i1 = min(i0 + 1, 1999);
        float w = pos - (float)i0;
        float v = f0b[i0] * (1.0f - w) + f0b[i1] * w;
        s += v * INV_SR;
    }
#pragma unroll
    for (int off = 16; off; off >>= 1)
        s += __shfl_down_sync(0xffffffffu, s, off);
    if (lane == 0) g_tot[b * NG + g] = s;
}

// ---------------- kernel 3: double exclusive wrapped scan + constants ----------------
__global__ void __launch_bounds__(1024) scan_kernel(
    const float* __restrict__ als, const float* __restrict__ pho,
    const float* __restrict__ lnv, const float* __restrict__ lnu)
{
    const int b = blockIdx.x;
    const int tid = threadIdx.x;

    if (b == 0 && tid < NHARM) {
        float e  = expf(als[tid]);
        float ph = TWO_PI_F * pho[tid];
        g_consts[tid]     = e * cosf(ph);
        g_consts[6 + tid] = e * sinf(ph);
        if (tid == 0) { g_consts[12] = expf(lnv[0]); g_consts[13] = expf(lnu[0]); }
    }

    const int PER = 8;                      // 1024*8 >= 7500
    const int s0 = tid * PER;
    float tl[PER];
    double loc = 0.0;
#pragma unroll
    for (int j = 0; j < PER; j++) {
        int idx = s0 + j;
        float t = (idx < NG) ? g_tot[b * NG + idx] : 0.0f;
        tl[j] = t;
        loc += (double)t;
    }
    __shared__ double sd[1024];
    sd[tid] = loc;
    __syncthreads();
    for (int off = 1; off < 1024; off <<= 1) {
        double add = (tid >= off) ? sd[tid - off] : 0.0;
        __syncthreads();
        sd[tid] += add;
        __syncthreads();
    }
    double base = (tid > 0) ? sd[tid - 1] : 0.0;
#pragma unroll
    for (int j = 0; j < PER; j++) {
        int idx = s0 + j;
        if (idx < NG)
            g_carry[b * NG + idx] = (float)(base - floor(base));
        base += (double)tl[j];
    }
}

// ---------------- kernel 4: main synthesis ----------------
// block = 128 threads; warp = one 128-sample group; thread = 4 samples
__global__ void __launch_bounds__(128) main_kernel(
    const float* __restrict__ f0, const float* __restrict__ noise,
    float* __restrict__ out)
{
    const int b    = blockIdx.y;
    const int warp = threadIdx.x >> 5;
    const int lane = threadIdx.x & 31;
    const int g    = blockIdx.x * 4 + warp;       // carry group 0..7499
    const int base = g * GRP + lane * 4;
    const float* f0b = f0 + b * T_FRAMES;

    float inc[4], f0v[4], wfr[4];
    int   ia[4];
#pragma unroll
    for (int j = 0; j < 4; j++) {
        int i = base + j;
        float pos = fmaf((float)i + 0.5f, SCALE_POS, -0.5f);
        pos = fminf(fmaxf(pos, 0.0f), 1999.0f);
        int i0 = (int)pos;
        int i1 = min(i0 + 1, 1999);
        float w = pos - (float)i0;
        ia[j] = i0; wfr[j] = w;
        float v = f0b[i0] * (1.0f - w) + f0b[i1] * w;
        f0v[j] = v;
        inc[j] = v * INV_SR;
    }

    float inc4 = ((inc[0] + inc[1]) + inc[2]) + inc[3];
    const unsigned FULL = 0xffffffffu;
    float v = inc4;
#pragma unroll
    for (int off = 1; off < 32; off <<= 1) {
        float n = __shfl_up_sync(FULL, v, off);
        if (lane >= off) v += n;
    }
    float running = g_carry[b * NG + g] + (v - inc4);   // exclusive prefix + carry

    float cA[6], cB[6];
#pragma unroll
    for (int h = 0; h < 6; h++) { cA[h] = g_consts[h]; cB[h] = g_consts[6 + h]; }
    const float nv = g_consts[12], nu = g_consts[13];

    float4 nz = *(const float4*)(noise + (size_t)b * T_AUD + base);
    const float* nzp = &nz.x;

    float och[7][4];
#pragma unroll
    for (int j = 0; j < 4; j++) {
        running += inc[j];
        float r  = running - rintf(running);           // [-0.5, 0.5], periodic-1
        float s1, c1;
        __sincosf(TWO_PI_F * r, &s1, &c1);
        float voiced = (f0v[j] > 1.0f) ? 1.0f : 0.0f;

        const float* ap = g_amp + ((size_t)b * T_FRAMES + ia[j]) * 8;
        int i1 = min(ia[j] + 1, 1999);
        const float* aq = g_amp + ((size_t)b * T_FRAMES + i1) * 8;
        float4 u0 = *(const float4*)ap;
        float4 u1 = *(const float4*)(ap + 4);
        float4 p0 = *(const float4*)aq;
        float4 p1 = *(const float4*)(aq + 4);
        float w = wfr[j], iw = 1.0f - w;
        float am[6] = { u0.x * iw + p0.x * w, u0.y * iw + p0.y * w,
                        u0.z * iw + p0.z * w, u0.w * iw + p0.w * w,
                        u1.x * iw + p1.x * w, u1.y * iw + p1.y * w };

        float sk = s1, ck = c1;
#pragma unroll
        for (int h = 0; h < 6; h++) {
            if (h) {
                float t = sk * c1 + ck * s1;
                ck = ck * c1 - sk * s1;
                sk = t;
            }
            float e    = __expf(-am[h]);
            float sig2 = __fdividef(2.0f, 1.0f + e);
            och[h][j] = (sk * cA[h] + ck * cB[h]) * (sig2 * voiced);
        }
        float na = (voiced > 0.0f) ? nv : nu;
        och[6][j] = nzp[j] * na;
    }

#pragma unroll
    for (int h = 0; h < 7; h++) {
        float4 o = make_float4(och[h][0], och[h][1], och[h][2], och[h][3]);
        *(float4*)(out + ((size_t)(b * 7 + h)) * T_AUD + base) = o;
    }
}

// ---------------- launcher ----------------
extern "C" void kernel_launch(void* const* d_in, const int* in_sizes, int n_in,
                              void* d_out, int out_size)
{
    const float* f0    = (const float*)d_in[0];
    const float* mel   = (const float*)d_in[1];
    const float* noise = (const float*)d_in[2];
    const float* w1    = (const float*)d_in[3];
    const float* b1    = (const float*)d_in[4];
    const float* w2    = (const float*)d_in[5];
    const float* b2    = (const float*)d_in[6];
    const float* als   = (const float*)d_in[7];
    const float* pho   = (const float*)d_in[8];
    const float* lnv   = (const float*)d_in[9];
    const float* lnu   = (const float*)d_in[10];
    float* out = (float*)d_out;

    totals_kernel<<<3750, 256>>>(f0);
    conv_kernel  <<<dim3(NTILE, NB), 256>>>(f0, mel, w1, b1, w2, b2);
    scan_kernel  <<<NB, 1024>>>(als, pho, lnv, lnu);
    main_kernel  <<<dim3(1875, NB), 128>>>(f0, noise, out);
}